// round 3
// baseline (speedup 1.0000x reference)
#include <cuda_runtime.h>
#include <cstdint>

#define NNODES 8192
#define FEAT   128
#define F4     32             // FEAT/4 float4 per row
#define CAP    128            // max (padded) nnz/row; Binomial(8192,0.004): P(>120) ~ 0

#define GEMM_BLOCKS 384       // 3 branches x 128 row-tiles
#define CSR_BLOCKS  1024      // 8 rows (warps) per block

// ---------------- device scratch (no allocations allowed) ----------------
__device__ __align__(16) int   g_nnz[NNODES];
__device__ __align__(16) int   g_col[NNODES * CAP];
__device__ __align__(16) float g_z1[NNODES * FEAT];
__device__ __align__(16) float g_z2[NNODES * FEAT];
// z3 / u0 / u1 have one extra ZERO row (index NNODES) used as gather pad target
__device__ __align__(16) float g_z3[(NNODES + 1) * FEAT];
__device__ __align__(16) float g_u0[(NNODES + 1) * FEAT];
__device__ __align__(16) float g_u1[(NNODES + 1) * FEAT];
__device__ int g_gemm_done;   // reset to 0 by memset each launch

// =====================================================================
// K1: heterogeneous kernel.
//   blocks [0, GEMM_BLOCKS)           : z_k = x @ W_k       (FMA-bound)
//   blocks [GEMM_BLOCKS, +CSR_BLOCKS) : CSR build of A      (HBM-bound)
//                                       + fused u0 = z2 + A z3
// GEMM blocks scheduled first; their FMA work + the fused spmm's L2
// gathers both hide under the 256MB HBM stream of A.
// =====================================================================
__global__ void __launch_bounds__(256, 4)
ib_build(const float* __restrict__ A,
         const float* __restrict__ x,
         const float* __restrict__ W1,
         const float* __restrict__ W2,
         const float* __restrict__ W3) {

    // shared memory overlay: GEMM tiles OR per-warp col lists
    __shared__ __align__(16) char smem_raw[64 * 33 * 4 + 32 * 128 * 4]; // 24832 B

    if (blockIdx.x < GEMM_BLOCKS) {
        // ---------------- GEMM branch: 64x128 tile, K-tiled by 32 ----------
        float (*xs)[33]  = reinterpret_cast<float(*)[33]>(smem_raw);
        float (*Ws)[128] = reinterpret_cast<float(*)[128]>(smem_raw + 64 * 33 * 4);

        int bz = blockIdx.x >> 7;          // 0..2  (branch)
        int bx = blockIdx.x & 127;         // row tile
        const float* W = (bz == 0) ? W1 : (bz == 1) ? W2 : W3;
        float* z       = (bz == 0) ? g_z1 : (bz == 1) ? g_z2 : g_z3;

        int tid = threadIdx.x;
        int tx = tid & 15;                  // cols tx*8 .. +7
        int ty = tid >> 4;                  // rows ty*4 .. +3
        int r0 = bx * 64;

        float acc[4][8];
        #pragma unroll
        for (int i = 0; i < 4; i++)
            #pragma unroll
            for (int j = 0; j < 8; j++) acc[i][j] = 0.0f;

        for (int kt = 0; kt < FEAT; kt += 32) {
            for (int idx = tid; idx < 64 * 32; idx += 256) {
                int rr = idx >> 5, kk = idx & 31;
                xs[rr][kk] = x[(size_t)(r0 + rr) * FEAT + kt + kk];
            }
            for (int idx = tid; idx < 32 * 128; idx += 256) {
                int kk = idx >> 7, cc = idx & 127;
                Ws[kk][cc] = W[(size_t)(kt + kk) * FEAT + cc];
            }
            __syncthreads();

            #pragma unroll
            for (int k = 0; k < 32; k++) {
                float4 b0 = *reinterpret_cast<const float4*>(&Ws[k][tx * 8]);
                float4 b1 = *reinterpret_cast<const float4*>(&Ws[k][tx * 8 + 4]);
                float bb[8] = {b0.x, b0.y, b0.z, b0.w, b1.x, b1.y, b1.z, b1.w};
                #pragma unroll
                for (int i = 0; i < 4; i++) {
                    float a = xs[ty * 4 + i][k];
                    #pragma unroll
                    for (int j = 0; j < 8; j++) acc[i][j] = fmaf(a, bb[j], acc[i][j]);
                }
            }
            __syncthreads();
        }

        #pragma unroll
        for (int i = 0; i < 4; i++) {
            float* dst = z + (size_t)(r0 + ty * 4 + i) * FEAT + tx * 8;
            *reinterpret_cast<float4*>(dst)     = make_float4(acc[i][0], acc[i][1], acc[i][2], acc[i][3]);
            *reinterpret_cast<float4*>(dst + 4) = make_float4(acc[i][4], acc[i][5], acc[i][6], acc[i][7]);
        }

        // signal completion (stores must be globally visible first)
        __syncthreads();
        __threadfence();
        if (tid == 0) atomicAdd(&g_gemm_done, 1);
        return;
    }

    // ---------------- CSR branch + fused u0 = z2 + A*z3 --------------------
    {
        int (*s_cols)[CAP] = reinterpret_cast<int(*)[CAP]>(smem_raw);
        int wid  = threadIdx.x >> 5;
        int lane = threadIdx.x & 31;
        int row  = (blockIdx.x - GEMM_BLOCKS) * 8 + wid;

        const float4* r4 = reinterpret_cast<const float4*>(A + (size_t)row * NNODES);
        int* sc = s_cols[wid];
        int base = 0;

        // 8 iterations x (8 coalesced float4/lane = 1024 columns/warp)
        #pragma unroll 1
        for (int it = 0; it < 8; it++) {
            float4 v[8];
            #pragma unroll
            for (int k = 0; k < 8; k++)
                v[k] = r4[it * 256 + k * 32 + lane];

            unsigned m = 0;
            #pragma unroll
            for (int k = 0; k < 8; k++) {
                m |= (unsigned)(v[k].x != 0.0f) << (k * 4 + 0);
                m |= (unsigned)(v[k].y != 0.0f) << (k * 4 + 1);
                m |= (unsigned)(v[k].z != 0.0f) << (k * 4 + 2);
                m |= (unsigned)(v[k].w != 0.0f) << (k * 4 + 3);
            }
            int cnt  = __popc(m);
            int incl = cnt;
            #pragma unroll
            for (int d = 1; d < 32; d <<= 1) {
                int t = __shfl_up_sync(0xffffffffu, incl, d);
                if (lane >= d) incl += t;
            }
            int myoff = base + incl - cnt;
            int total = __shfl_sync(0xffffffffu, incl, 31);

            while (m) {
                int b = __ffs(m) - 1;            // b = k*4 + comp
                m &= m - 1;
                int col = it * 1024 + (b >> 2) * 128 + lane * 4 + (b & 3);
                if (myoff < CAP) sc[myoff] = col;
                myoff++;
            }
            base += total;
        }

        int nnz  = base < CAP ? base : CAP;
        int nnzp = (nnz + 7) & ~7;               // pad to multiple of 8
        if (nnzp > CAP) nnzp = CAP;
        for (int j = nnz + lane; j < nnzp; j += 32) sc[j] = NNODES;  // zero-row pad
        __syncwarp();

        // persist CSR (coalesced within warp)
        int* cp = g_col + row * CAP;
        for (int j = lane; j < nnzp; j += 32) cp[j] = sc[j];
        if (lane == 0) g_nnz[row] = nnzp;

        // ---- fused spmm pass 1: u0[row] = z2[row] + sum z3[c] ----
        if (lane == 0) {
            while (*(volatile int*)&g_gemm_done < GEMM_BLOCKS) __nanosleep(100);
        }
        __syncwarp();
        __threadfence();   // acquire: GEMM stores visible

        const float4* z2 = reinterpret_cast<const float4*>(g_z2);
        const float4* z3 = reinterpret_cast<const float4*>(g_z3);
        float4* u0       = reinterpret_cast<float4*>(g_u0);

        float4 acc = z2[(size_t)row * F4 + lane];
        for (int i = 0; i < nnzp; i += 8) {
            float4 w[8];
            #pragma unroll
            for (int j = 0; j < 8; j++)
                w[j] = z3[(size_t)sc[i + j] * F4 + lane];
            #pragma unroll
            for (int j = 0; j < 8; j++) {
                acc.x += w[j].x; acc.y += w[j].y; acc.z += w[j].z; acc.w += w[j].w;
            }
        }
        u0[(size_t)row * F4 + lane] = acc;
    }
}

// =====================================================================
// K2: SpMM pass, warp-per-row, padded col list -> branch-free batches.
//   out[r] = scale * (add[r] + sum_j yin[col_j])
// =====================================================================
__global__ void __launch_bounds__(256, 8)
ib_spmm(float4* __restrict__ out,
        const float4* __restrict__ yin,
        const float4* __restrict__ addv,
        float scale) {
    __shared__ int s_cols[8][CAP];

    int wid  = threadIdx.x >> 5;
    int lane = threadIdx.x & 31;
    int row  = blockIdx.x * 8 + wid;

    int nnzp = g_nnz[row];                       // already multiple of 8
    const int* cp = g_col + row * CAP;
    int* sc = s_cols[wid];
    for (int j = lane; j < nnzp; j += 32) sc[j] = cp[j];
    __syncwarp();

    float4 acc = addv ? addv[(size_t)row * F4 + lane]
                      : make_float4(0.f, 0.f, 0.f, 0.f);

    for (int i = 0; i < nnzp; i += 8) {
        float4 v[8];
        #pragma unroll
        for (int j = 0; j < 8; j++)
            v[j] = yin[(size_t)sc[i + j] * F4 + lane];
        #pragma unroll
        for (int j = 0; j < 8; j++) {
            acc.x += v[j].x; acc.y += v[j].y; acc.z += v[j].z; acc.w += v[j].w;
        }
    }

    acc.x *= scale; acc.y *= scale; acc.z *= scale; acc.w *= scale;
    out[(size_t)row * F4 + lane] = acc;
}

// ---------------- launch ----------------
extern "C" void kernel_launch(void* const* d_in, const int* in_sizes, int n_in,
                              void* d_out, int out_size) {
    const float* x  = (const float*)d_in[0];
    const float* A  = (const float*)d_in[1];
    const float* W1 = (const float*)d_in[2];
    const float* W2 = (const float*)d_in[3];
    const float* W3 = (const float*)d_in[4];
    float4* out = (float4*)d_out;

    float *z1f, *z3f, *u0f, *u1f; int* donep;
    cudaGetSymbolAddress((void**)&z1f,  g_z1);
    cudaGetSymbolAddress((void**)&z3f,  g_z3);
    cudaGetSymbolAddress((void**)&u0f,  g_u0);
    cudaGetSymbolAddress((void**)&u1f,  g_u1);
    cudaGetSymbolAddress((void**)&donep, g_gemm_done);

    // per-launch resets (replay-deterministic): flag + the 3 zero pad rows
    cudaMemsetAsync(donep, 0, sizeof(int));
    cudaMemsetAsync(z3f + (size_t)NNODES * FEAT, 0, FEAT * sizeof(float));
    cudaMemsetAsync(u0f + (size_t)NNODES * FEAT, 0, FEAT * sizeof(float));
    cudaMemsetAsync(u1f + (size_t)NNODES * FEAT, 0, FEAT * sizeof(float));

    // K1: GEMM (z1,z2,z3) + CSR build + fused u0 = z2 + A*z3
    ib_build<<<GEMM_BLOCKS + CSR_BLOCKS, 256>>>(A, x, W1, W2, W3);

    // remaining Horner steps: u1 = z1 + A*u0 ; out = (A*u1)/3
    ib_spmm<<<NNODES / 8, 256>>>((float4*)u1f, (const float4*)u0f, (const float4*)z1f, 1.0f);
    ib_spmm<<<NNODES / 8, 256>>>(out, (const float4*)u1f, nullptr, 1.0f / 3.0f);
}

// round 4
// speedup vs baseline: 1.2438x; 1.2438x over previous
#include <cuda_runtime.h>
#include <cstdint>

#define NNODES 8192
#define FEAT   128
#define F4     32             // FEAT/4 float4 per row
#define CAP    128            // max (padded) nnz/row; Binomial(8192,0.004): P(>120) ~ 0

#define GEMM_BLOCKS 768       // 3 branches x 128 row-tiles x 2 col-halves
#define CSR_BLOCKS  1024      // 8 rows (warps) per block

// ---------------- device scratch (no allocations allowed) ----------------
// NOTE: __device__ globals are zero-initialized at module load. The pad rows
// (index NNODES) of z3/u0/u1 are NEVER written by any kernel, so they remain
// zero across all graph replays — no per-launch reset needed.
__device__ __align__(16) int   g_nnz[NNODES];
__device__ __align__(16) int   g_col[NNODES * CAP];
__device__ __align__(16) float g_z1[NNODES * FEAT];
__device__ __align__(16) float g_z2[NNODES * FEAT];
__device__ __align__(16) float g_z3[(NNODES + 1) * FEAT];
__device__ __align__(16) float g_u0[(NNODES + 1) * FEAT];
__device__ __align__(16) float g_u1[(NNODES + 1) * FEAT];

// =====================================================================
// K1: heterogeneous kernel, register-balanced.
//   blocks [0, GEMM_BLOCKS)           : z_k = x @ W_k   (64x64 tiles, FMA)
//   blocks [GEMM_BLOCKS, +CSR_BLOCKS) : CSR build of A  (HBM stream)
// launch_bounds(256,5) caps regs at ~51 so the HBM branch gets ~40
// resident warps/SM for latency hiding.
// =====================================================================
__global__ void __launch_bounds__(256, 5)
ib_build(const float* __restrict__ A,
         const float* __restrict__ x,
         const float* __restrict__ W1,
         const float* __restrict__ W2,
         const float* __restrict__ W3) {

    // overlay: GEMM tiles (16640B) or per-warp col lists (4096B)
    __shared__ __align__(16) char smem_raw[64 * 33 * 4 + 32 * 64 * 4];

    if (blockIdx.x < GEMM_BLOCKS) {
        // -------- GEMM branch: 64 rows x 64 cols per block, K-tiled by 32 ----
        float (*xs)[33] = reinterpret_cast<float(*)[33]>(smem_raw);
        float (*Ws)[64] = reinterpret_cast<float(*)[64]>(smem_raw + 64 * 33 * 4);

        int bz  = blockIdx.x >> 8;          // branch 0..2
        int rem = blockIdx.x & 255;
        int bx  = rem >> 1;                 // row tile 0..127
        int bc  = rem & 1;                  // col half 0/1
        const float* W = (bz == 0) ? W1 : (bz == 1) ? W2 : W3;
        float* z       = (bz == 0) ? g_z1 : (bz == 1) ? g_z2 : g_z3;

        int tid = threadIdx.x;
        int tx  = tid & 15;                 // cols c0 + tx*4 .. +3
        int ty  = tid >> 4;                 // rows r0 + ty*4 .. +3
        int r0  = bx * 64;
        int c0  = bc * 64;

        float acc[4][4];
        #pragma unroll
        for (int i = 0; i < 4; i++)
            #pragma unroll
            for (int j = 0; j < 4; j++) acc[i][j] = 0.0f;

        for (int kt = 0; kt < FEAT; kt += 32) {
            #pragma unroll
            for (int l = 0; l < 8; l++) {
                int idx = tid + l * 256;
                int rr = idx >> 5, kk = idx & 31;
                xs[rr][kk] = x[(size_t)(r0 + rr) * FEAT + kt + kk];
            }
            #pragma unroll
            for (int l = 0; l < 8; l++) {
                int idx = tid + l * 256;
                int kk = idx >> 6, cc = idx & 63;
                Ws[kk][cc] = W[(size_t)(kt + kk) * FEAT + c0 + cc];
            }
            __syncthreads();

            #pragma unroll
            for (int k = 0; k < 32; k++) {
                float4 b = *reinterpret_cast<const float4*>(&Ws[k][tx * 4]);
                float bb[4] = {b.x, b.y, b.z, b.w};
                #pragma unroll
                for (int i = 0; i < 4; i++) {
                    float a = xs[ty * 4 + i][k];
                    #pragma unroll
                    for (int j = 0; j < 4; j++) acc[i][j] = fmaf(a, bb[j], acc[i][j]);
                }
            }
            __syncthreads();
        }

        #pragma unroll
        for (int i = 0; i < 4; i++) {
            float* dst = z + (size_t)(r0 + ty * 4 + i) * FEAT + c0 + tx * 4;
            *reinterpret_cast<float4*>(dst) =
                make_float4(acc[i][0], acc[i][1], acc[i][2], acc[i][3]);
        }
        return;
    }

    // -------- CSR branch: warp-per-row, streaming loads, padded output ------
    {
        int (*s_cols)[CAP] = reinterpret_cast<int(*)[CAP]>(smem_raw);
        int wid  = threadIdx.x >> 5;
        int lane = threadIdx.x & 31;
        int row  = (blockIdx.x - GEMM_BLOCKS) * 8 + wid;

        const float4* r4 = reinterpret_cast<const float4*>(A + (size_t)row * NNODES);
        int* sc = s_cols[wid];
        int base = 0;

        // 8 iterations x 1024 columns (8 coalesced float4 per lane, streamed)
        #pragma unroll 1
        for (int it = 0; it < 8; it++) {
            float4 v[8];
            #pragma unroll
            for (int k = 0; k < 8; k++)
                v[k] = __ldcs(&r4[it * 256 + k * 32 + lane]);

            unsigned m = 0;
            #pragma unroll
            for (int k = 0; k < 8; k++) {
                m |= (unsigned)(v[k].x != 0.0f) << (k * 4 + 0);
                m |= (unsigned)(v[k].y != 0.0f) << (k * 4 + 1);
                m |= (unsigned)(v[k].z != 0.0f) << (k * 4 + 2);
                m |= (unsigned)(v[k].w != 0.0f) << (k * 4 + 3);
            }
            int cnt  = __popc(m);
            int incl = cnt;
            #pragma unroll
            for (int d = 1; d < 32; d <<= 1) {
                int t = __shfl_up_sync(0xffffffffu, incl, d);
                if (lane >= d) incl += t;
            }
            int myoff = base + incl - cnt;
            int total = __shfl_sync(0xffffffffu, incl, 31);

            while (m) {
                int b = __ffs(m) - 1;                 // b = k*4 + comp
                m &= m - 1;
                int col = it * 1024 + ((b >> 2) << 7) + (lane << 2) + (b & 3);
                if (myoff < CAP) sc[myoff] = col;
                myoff++;
            }
            base += total;
        }

        int nnz  = base < CAP ? base : CAP;
        int nnzp = (nnz + 7) & ~7;                    // pad to multiple of 8
        if (nnzp > CAP) nnzp = CAP;
        for (int j = nnz + lane; j < nnzp; j += 32) sc[j] = NNODES;  // zero-row pad
        __syncwarp();

        int* cp = g_col + row * CAP;
        for (int j = lane; j < nnzp; j += 32) cp[j] = sc[j];
        if (lane == 0) g_nnz[row] = nnzp;
    }
}

// =====================================================================
// K2: SpMM pass, warp-per-row, padded col list -> branch-free batches.
//   out[r] = scale * (add[r] + sum_j yin[col_j])
// =====================================================================
__global__ void __launch_bounds__(256, 8)
ib_spmm(float4* __restrict__ out,
        const float4* __restrict__ yin,
        const float4* __restrict__ addv,
        float scale) {
    __shared__ int s_cols[8][CAP];

    int wid  = threadIdx.x >> 5;
    int lane = threadIdx.x & 31;
    int row  = blockIdx.x * 8 + wid;

    int nnzp = g_nnz[row];                            // multiple of 8
    const int* cp = g_col + row * CAP;
    int* sc = s_cols[wid];
    for (int j = lane; j < nnzp; j += 32) sc[j] = cp[j];
    __syncwarp();

    float4 acc = addv ? addv[(size_t)row * F4 + lane]
                      : make_float4(0.f, 0.f, 0.f, 0.f);

    for (int i = 0; i < nnzp; i += 8) {
        float4 v[8];
        #pragma unroll
        for (int j = 0; j < 8; j++)
            v[j] = yin[(size_t)sc[i + j] * F4 + lane];
        #pragma unroll
        for (int j = 0; j < 8; j++) {
            acc.x += v[j].x; acc.y += v[j].y; acc.z += v[j].z; acc.w += v[j].w;
        }
    }

    acc.x *= scale; acc.y *= scale; acc.z *= scale; acc.w *= scale;
    out[(size_t)row * F4 + lane] = acc;
}

// ---------------- launch ----------------
extern "C" void kernel_launch(void* const* d_in, const int* in_sizes, int n_in,
                              void* d_out, int out_size) {
    const float* x  = (const float*)d_in[0];
    const float* A  = (const float*)d_in[1];
    const float* W1 = (const float*)d_in[2];
    const float* W2 = (const float*)d_in[3];
    const float* W3 = (const float*)d_in[4];
    float4* out = (float4*)d_out;

    float *z1f, *z2f, *z3f, *u0f, *u1f;
    cudaGetSymbolAddress((void**)&z1f, g_z1);
    cudaGetSymbolAddress((void**)&z2f, g_z2);
    cudaGetSymbolAddress((void**)&z3f, g_z3);
    cudaGetSymbolAddress((void**)&u0f, g_u0);
    cudaGetSymbolAddress((void**)&u1f, g_u1);

    // K1: GEMM (z1,z2,z3) + CSR build, overlapped in one grid
    ib_build<<<GEMM_BLOCKS + CSR_BLOCKS, 256>>>(A, x, W1, W2, W3);

    // Horner: out = A*(z1 + A*(z2 + A*z3)) / 3
    ib_spmm<<<NNODES / 8, 256>>>((float4*)u0f, (const float4*)z3f, (const float4*)z2f, 1.0f);
    ib_spmm<<<NNODES / 8, 256>>>((float4*)u1f, (const float4*)u0f, (const float4*)z1f, 1.0f);
    ib_spmm<<<NNODES / 8, 256>>>(out, (const float4*)u1f, nullptr, 1.0f / 3.0f);
}